// round 1
// baseline (speedup 1.0000x reference)
#include <cuda_runtime.h>
#include <math.h>

#define NN 1024
#define HD 64
#define HH 8
#define ER 16384

// Scratch (allocation-free rule: __device__ globals)
__device__ int   g_claim[NN * NN];   // 4 MB: last edge index claiming (src,dst)
__device__ float g_Q[NN * HD];
__device__ float g_K[NN * HD];
__device__ float g_V[NN * HD];
__device__ float g_SV[HD];           // column sums of V
__device__ float g_acc[NN * HD];     // edge-delta value accumulator
__device__ float g_z[NN * HH];       // edge-delta normalizer accumulator

__global__ void init_kernel() {
    int i = blockIdx.x * blockDim.x + threadIdx.x;
    int stride = gridDim.x * blockDim.x;
    for (int idx = i; idx < NN * NN; idx += stride) g_claim[idx] = -1;
    for (int idx = i; idx < NN * HD; idx += stride) g_acc[idx] = 0.f;
    for (int idx = i; idx < NN * HH; idx += stride) g_z[idx] = 0.f;
    if (i < HD) g_SV[i] = 0.f;
}

// Q/K/V = h @ W, plus SV = column sums of V. One block = 16 nodes.
// blockDim = 192: tid>>6 selects matrix (0=Q,1=K,2=V), tid&63 = output column.
__global__ void nodeproj_kernel(const float* __restrict__ h,
                                const float* __restrict__ WQ,
                                const float* __restrict__ WK,
                                const float* __restrict__ WV) {
    __shared__ float hs[16 * 64];
    int tid = threadIdx.x;
    int i0 = blockIdx.x * 16;
    for (int idx = tid; idx < 16 * 64; idx += blockDim.x)
        hs[idx] = h[i0 * 64 + idx];
    __syncthreads();

    int c = tid & 63;
    int m = tid >> 6;  // 0,1,2
    const float* W = (m == 0) ? WQ : (m == 1) ? WK : WV;

    float acc[16];
#pragma unroll
    for (int i = 0; i < 16; i++) acc[i] = 0.f;
#pragma unroll 16
    for (int k = 0; k < 64; k++) {
        float wv = W[k * 64 + c];
#pragma unroll
        for (int i = 0; i < 16; i++) acc[i] = fmaf(hs[i * 64 + k], wv, acc[i]);
    }
    float* dstp = (m == 0) ? g_Q : (m == 1) ? g_K : g_V;
    float sv = 0.f;
#pragma unroll
    for (int i = 0; i < 16; i++) {
        dstp[(i0 + i) * 64 + c] = acc[i];
        sv += acc[i];
    }
    if (m == 2) atomicAdd(&g_SV[c], sv);
}

// Deterministic dedup: last duplicate edge (max index) wins, matching
// sequential scatter-set semantics.
__global__ void claim_kernel(const int* __restrict__ src,
                             const int* __restrict__ dst) {
    int k = blockIdx.x * blockDim.x + threadIdx.x;
    if (k >= ER) return;
    int s = src[k], d = dst[k];
    if (s != d) atomicMax(&g_claim[s * NN + d], k);
}

// One warp per edge; WE staged in smem per block (8 edges/block).
__global__ void __launch_bounds__(256) edge_kernel(
    const float* __restrict__ e,
    const float* __restrict__ WE,
    const int* __restrict__ src,
    const int* __restrict__ dst) {
    __shared__ float WEs[64 * 64];
    __shared__ float ebuf[8][64];
    int tid = threadIdx.x;
    for (int idx = tid; idx < 4096; idx += 256) WEs[idx] = WE[idx];
    __syncthreads();

    int w = tid >> 5, lane = tid & 31;
    int k = blockIdx.x * 8 + w;
    int s = src[k], d = dst[k];
    if (s == d) return;                       // self-loops zeroed by diagonal rule
    if (g_claim[s * NN + d] != k) return;     // superseded duplicate

    float2 ev = reinterpret_cast<const float2*>(e + (size_t)k * 64)[lane];
    ebuf[w][2 * lane] = ev.x;
    ebuf[w][2 * lane + 1] = ev.y;
    __syncwarp();

    // Ehe[c] = e_k @ WE[:,c], lane covers c=lane and c=lane+32
    float a0 = 0.f, a1 = 0.f;
#pragma unroll
    for (int kk = 0; kk < 64; kk++) {
        float evv = ebuf[w][kk];
        a0 = fmaf(evv, WEs[kk * 64 + lane], a0);
        a1 = fmaf(evv, WEs[kk * 64 + lane + 32], a1);
    }

    // 3-way contraction per head: c = h*8+d, groups of 8 lanes share a head
    float p0 = a0 * g_K[s * 64 + lane] * g_Q[d * 64 + lane];
    float p1 = a1 * g_K[s * 64 + lane + 32] * g_Q[d * 64 + lane + 32];
#pragma unroll
    for (int off = 4; off; off >>= 1) {
        p0 += __shfl_xor_sync(0xffffffffu, p0, off);
        p1 += __shfl_xor_sync(0xffffffffu, p1, off);
    }

    const float INVS = 0.35355339059327373f;  // 1/sqrt(8)
    const float SC   = 0.9090909090909091f;   // 1/(1+gamma)
    const float C0   = 0.09090909090909091f;  // gamma/(1+gamma)
    float d0 = expf(fminf(fmaxf(p0 * INVS, -5.f), 5.f)) * SC - C0;
    float d1 = expf(fminf(fmaxf(p1 * INVS, -5.f), 5.f)) * SC - C0;

    atomicAdd(&g_acc[d * 64 + lane],      d0 * g_V[s * 64 + lane]);
    atomicAdd(&g_acc[d * 64 + lane + 32], d1 * g_V[s * 64 + lane + 32]);
    if ((lane & 7) == 0) {
        atomicAdd(&g_z[d * 8 + (lane >> 3)],     d0);
        atomicAdd(&g_z[d * 8 + 4 + (lane >> 3)], d1);
    }
}

__global__ void final_kernel(float* __restrict__ out) {
    int idx = blockIdx.x * blockDim.x + threadIdx.x;
    if (idx >= NN * HD) return;
    int j = idx >> 6;
    int c = idx & 63;
    int hh = c >> 3;
    const float C0 = 0.09090909090909091f;
    float z = C0 * (float)(NN - 1) + g_z[j * 8 + hh] + 1e-6f;
    out[idx] = (C0 * (g_SV[c] - g_V[idx]) + g_acc[idx]) / z;
}

extern "C" void kernel_launch(void* const* d_in, const int* in_sizes, int n_in,
                              void* d_out, int out_size) {
    const float* h  = (const float*)d_in[0];
    const float* e  = (const float*)d_in[1];
    const float* WQ = (const float*)d_in[2];
    const float* WK = (const float*)d_in[3];
    const float* WE = (const float*)d_in[4];
    // d_in[5..7] = WQ2, WK2, WE2: provably unobservable (fake weights survive
    // only off-edge, where they equal the constant gamma/(1+gamma)).
    const float* WV = (const float*)d_in[8];
    const int* rs   = (const int*)d_in[9];
    const int* rd   = (const int*)d_in[10];
    float* out = (float*)d_out;

    init_kernel<<<2048, 512>>>();
    nodeproj_kernel<<<64, 192>>>(h, WQ, WK, WV);
    claim_kernel<<<64, 256>>>(rs, rd);
    edge_kernel<<<2048, 256>>>(e, WE, rs, rd);
    final_kernel<<<256, 256>>>(out);
}

// round 2
// speedup vs baseline: 1.3161x; 1.3161x over previous
#include <cuda_runtime.h>
#include <math.h>

#define NN 1024
#define HD 64
#define ER 16384
#define ESTR 68   // padded smem stride (multiple of 4 for float4 alignment)

// Scratch (allocation-free rule: __device__ globals)
__device__ int   g_claim[NN * NN];   // 4 MB: last edge index claiming (src,dst)
__device__ float g_Q[NN * HD];
__device__ float g_K[NN * HD];
__device__ float g_V[NN * HD];
__device__ float g_SV[HD];           // column sums of V
__device__ float g_acc[NN * HD];     // edge-delta value accumulator
__device__ float g_z[NN * 8];        // edge-delta normalizer accumulator

// ---------------------------------------------------------------- init
__global__ void init_kernel() {
    int i = blockIdx.x * blockDim.x + threadIdx.x;   // 262144 threads
    int4* c4 = (int4*)g_claim;                        // 262144 int4
    c4[i] = make_int4(-1, -1, -1, -1);
    if (i < (NN * HD) / 4) ((float4*)g_acc)[i] = make_float4(0.f, 0.f, 0.f, 0.f);
    if (i < (NN * 8) / 4)  ((float4*)g_z)[i]   = make_float4(0.f, 0.f, 0.f, 0.f);
    if (i < HD)            g_SV[i] = 0.f;
}

// -------------------------------------------- node projections + claim pass
// blocks 0..127: Q/K/V projection (8 nodes each). blocks 128..143: edge claim.
__global__ void __launch_bounds__(192) proj_claim_kernel(
    const float* __restrict__ h,
    const float* __restrict__ WQ,
    const float* __restrict__ WK,
    const float* __restrict__ WV,
    const int* __restrict__ src,
    const int* __restrict__ dst) {
    int b = blockIdx.x;
    int tid = threadIdx.x;
    if (b >= 128) {
        // claim: deterministic dedup, last duplicate (max index) wins
        int cb = b - 128;
        int base = cb * 1024;
        for (int k = base + tid; k < base + 1024; k += 192) {
            int s = src[k], d = dst[k];
            if (s != d) atomicMax(&g_claim[s * NN + d], k);
        }
        return;
    }
    __shared__ float hs[8 * 64];
    int i0 = b * 8;
    for (int idx = tid; idx < 512; idx += 192) hs[idx] = h[i0 * 64 + idx];
    __syncthreads();

    int c = tid & 63;
    int m = tid >> 6;  // 0=Q,1=K,2=V
    const float* W = (m == 0) ? WQ : (m == 1) ? WK : WV;
    float acc[8];
#pragma unroll
    for (int i = 0; i < 8; i++) acc[i] = 0.f;
#pragma unroll 16
    for (int k = 0; k < 64; k++) {
        float wv = W[k * 64 + c];
#pragma unroll
        for (int i = 0; i < 8; i++) acc[i] = fmaf(hs[i * 64 + k], wv, acc[i]);
    }
    float* dstp = (m == 0) ? g_Q : (m == 1) ? g_K : g_V;
    float sv = 0.f;
#pragma unroll
    for (int i = 0; i < 8; i++) {
        dstp[(i0 + i) * 64 + c] = acc[i];
        sv += acc[i];
    }
    if (m == 2) atomicAdd(&g_SV[c], sv);
}

// ---------------------------------------------------------------- fused edge
// Block = 64 edges. Phase 1: tiled GEMM Ehe = e_tile @ WE (f32x2 packed FMA).
// Phase 2: per-edge 3-way contraction + exp + scatter atomics.
__global__ void __launch_bounds__(256) edge_kernel(
    const float* __restrict__ e,
    const float* __restrict__ WE,
    const int* __restrict__ src,
    const int* __restrict__ dst) {
    __shared__ __align__(16) float WEs[64 * 64];     // [k][c]
    __shared__ __align__(16) float buf[64 * ESTR];   // es[k][edge], later ehe[edge][c]
    __shared__ int s_sh[64], d_sh[64];

    int tid = threadIdx.x;
    int base = blockIdx.x * 64;

    if (tid < 64) { s_sh[tid] = src[base + tid]; d_sh[tid] = dst[base + tid]; }

    // stage WE
    {
        float4* w4 = (float4*)WEs;
        const float4* g4 = (const float4*)WE;
        for (int idx = tid; idx < 1024; idx += 256) w4[idx] = g4[idx];
    }
    // stage e-tile transposed: es[k][edge]
    {
        int el = tid >> 2, seg = tid & 3;  // 4 threads per edge row, 16 floats each
        const float4* ge = (const float4*)(e + (size_t)(base + el) * 64 + seg * 16);
#pragma unroll
        for (int q = 0; q < 4; q++) {
            float4 v = ge[q];
            int k0 = seg * 16 + q * 4;
            buf[(k0 + 0) * ESTR + el] = v.x;
            buf[(k0 + 1) * ESTR + el] = v.y;
            buf[(k0 + 2) * ESTR + el] = v.z;
            buf[(k0 + 3) * ESTR + el] = v.w;
        }
    }
    __syncthreads();

    // GEMM: thread (tx,ty) computes edges ty*4..+3  x  cols tx*4..+3
    int tx = tid & 15, ty = tid >> 4;
    unsigned long long acc[4][2];
#pragma unroll
    for (int i = 0; i < 4; i++) { acc[i][0] = 0ULL; acc[i][1] = 0ULL; }

#pragma unroll 16
    for (int k = 0; k < 64; k++) {
        float4 av = *reinterpret_cast<const float4*>(&buf[k * ESTR + ty * 4]);
        ulonglong2 bv = *reinterpret_cast<const ulonglong2*>(&WEs[k * 64 + tx * 4]);
        unsigned long long ad0, ad1, ad2, ad3;
        asm("mov.b64 %0, {%1,%1};" : "=l"(ad0) : "f"(av.x));
        asm("mov.b64 %0, {%1,%1};" : "=l"(ad1) : "f"(av.y));
        asm("mov.b64 %0, {%1,%1};" : "=l"(ad2) : "f"(av.z));
        asm("mov.b64 %0, {%1,%1};" : "=l"(ad3) : "f"(av.w));
        asm("fma.rn.f32x2 %0, %1, %2, %0;" : "+l"(acc[0][0]) : "l"(ad0), "l"(bv.x));
        asm("fma.rn.f32x2 %0, %1, %2, %0;" : "+l"(acc[0][1]) : "l"(ad0), "l"(bv.y));
        asm("fma.rn.f32x2 %0, %1, %2, %0;" : "+l"(acc[1][0]) : "l"(ad1), "l"(bv.x));
        asm("fma.rn.f32x2 %0, %1, %2, %0;" : "+l"(acc[1][1]) : "l"(ad1), "l"(bv.y));
        asm("fma.rn.f32x2 %0, %1, %2, %0;" : "+l"(acc[2][0]) : "l"(ad2), "l"(bv.x));
        asm("fma.rn.f32x2 %0, %1, %2, %0;" : "+l"(acc[2][1]) : "l"(ad2), "l"(bv.y));
        asm("fma.rn.f32x2 %0, %1, %2, %0;" : "+l"(acc[3][0]) : "l"(ad3), "l"(bv.x));
        asm("fma.rn.f32x2 %0, %1, %2, %0;" : "+l"(acc[3][1]) : "l"(ad3), "l"(bv.y));
    }
    __syncthreads();  // all reads of es done before overwrite

    // write Ehe[edge][c] over buf (stride ESTR keeps 16B alignment)
#pragma unroll
    for (int i = 0; i < 4; i++) {
        float2 lo = *reinterpret_cast<float2*>(&acc[i][0]);
        float2 hi = *reinterpret_cast<float2*>(&acc[i][1]);
        float4 o = make_float4(lo.x, lo.y, hi.x, hi.y);
        *reinterpret_cast<float4*>(&buf[(ty * 4 + i) * ESTR + tx * 4]) = o;
    }
    __syncthreads();

    // Phase 2: warp w handles edges w*8 .. w*8+7
    int w = tid >> 5, lane = tid & 31;
    // prefetch claims for this warp's 8 edges (lanes 0..7 carry distinct edges)
    int mk = w * 8 + (lane & 7);
    int ms = s_sh[mk], md = d_sh[mk];
    int cl = (ms == md) ? -2 : g_claim[ms * NN + md];

    const float INVS = 0.35355339059327373f;  // 1/sqrt(8)
    const float SC   = 0.9090909090909091f;   // 1/(1+gamma)
    const float C0   = 0.09090909090909091f;  // gamma/(1+gamma)

#pragma unroll
    for (int i = 0; i < 8; i++) {
        int kl = w * 8 + i;
        int cv = __shfl_sync(0xffffffffu, cl, i);
        if (cv != base + kl) continue;  // self-loop or superseded duplicate
        int s = s_sh[kl], d = d_sh[kl];
        float eh0 = buf[kl * ESTR + lane];
        float eh1 = buf[kl * ESTR + lane + 32];
        float p0 = eh0 * g_K[s * 64 + lane] * g_Q[d * 64 + lane];
        float p1 = eh1 * g_K[s * 64 + lane + 32] * g_Q[d * 64 + lane + 32];
#pragma unroll
        for (int off = 4; off; off >>= 1) {
            p0 += __shfl_xor_sync(0xffffffffu, p0, off);
            p1 += __shfl_xor_sync(0xffffffffu, p1, off);
        }
        float d0 = expf(fminf(fmaxf(p0 * INVS, -5.f), 5.f)) * SC - C0;
        float d1 = expf(fminf(fmaxf(p1 * INVS, -5.f), 5.f)) * SC - C0;
        atomicAdd(&g_acc[d * 64 + lane],      d0 * g_V[s * 64 + lane]);
        atomicAdd(&g_acc[d * 64 + lane + 32], d1 * g_V[s * 64 + lane + 32]);
        if ((lane & 7) == 0) {
            atomicAdd(&g_z[d * 8 + (lane >> 3)],     d0);
            atomicAdd(&g_z[d * 8 + 4 + (lane >> 3)], d1);
        }
    }
}

// ---------------------------------------------------------------- finalize
__global__ void final_kernel(float* __restrict__ out) {
    int idx = blockIdx.x * blockDim.x + threadIdx.x;
    if (idx >= NN * HD) return;
    int j = idx >> 6;
    int c = idx & 63;
    int hh = c >> 3;
    const float C0 = 0.09090909090909091f;
    float z = C0 * (float)(NN - 1) + g_z[j * 8 + hh] + 1e-6f;
    out[idx] = (C0 * (g_SV[c] - g_V[idx]) + g_acc[idx]) / z;
}

extern "C" void kernel_launch(void* const* d_in, const int* in_sizes, int n_in,
                              void* d_out, int out_size) {
    const float* h  = (const float*)d_in[0];
    const float* e  = (const float*)d_in[1];
    const float* WQ = (const float*)d_in[2];
    const float* WK = (const float*)d_in[3];
    const float* WE = (const float*)d_in[4];
    // d_in[5..7] = WQ2, WK2, WE2: unobservable (fake weights survive only
    // off-edge, where they equal the constant gamma/(1+gamma)).
    const float* WV = (const float*)d_in[8];
    const int* rs   = (const int*)d_in[9];
    const int* rd   = (const int*)d_in[10];
    float* out = (float*)d_out;

    init_kernel<<<1024, 256>>>();
    proj_claim_kernel<<<144, 192>>>(h, WQ, WK, WV, rs, rd);
    edge_kernel<<<256, 256>>>(e, WE, rs, rd);
    final_kernel<<<256, 256>>>(out);
}

// round 3
// speedup vs baseline: 1.3278x; 1.0089x over previous
#include <cuda_runtime.h>
#include <math.h>

#define NN 1024
#define HD 64
#define ER 16384
#define ESTR 68   // padded smem stride (multiple of 4 for float4 alignment)

// Scratch (allocation-free rule: __device__ globals).
// Self-cleaning state machine: all of these are zero at module load and are
// returned to zero by final_kernel each run, so no init launch is needed.
__device__ int   g_claim[NN * NN];     // 0 = empty; claim value = edge_idx+1
__device__ float g_Q[NN * HD];
__device__ float g_K[NN * HD];
__device__ float g_V[NN * HD];
__device__ float g_SVp[128 * 64];      // per-proj-block partial V column sums (always overwritten)
__device__ float g_acc[NN * HD];       // edge-delta value accumulator (self-reset in final)
__device__ float g_z[NN * 8];          // edge-delta normalizer (reset in final)

// -------------------------------------------- node projections + claim pass
// blocks 0..127: Q/K/V projection (8 nodes each). blocks 128..143: edge claim.
__global__ void __launch_bounds__(192) proj_claim_kernel(
    const float* __restrict__ h,
    const float* __restrict__ WQ,
    const float* __restrict__ WK,
    const float* __restrict__ WV,
    const int* __restrict__ src,
    const int* __restrict__ dst) {
    int b = blockIdx.x;
    int tid = threadIdx.x;
    if (b >= 128) {
        // claim: deterministic dedup, last duplicate (max index) wins
        int base = (b - 128) * 1024;
        for (int k = base + tid; k < base + 1024; k += 192) {
            int s = src[k], d = dst[k];
            if (s != d) atomicMax(&g_claim[s * NN + d], k + 1);
        }
        return;
    }
    __shared__ float hs[8 * 64];
    int i0 = b * 8;
    for (int idx = tid; idx < 512; idx += 192) hs[idx] = h[i0 * 64 + idx];
    __syncthreads();

    int c = tid & 63;
    int m = tid >> 6;  // 0=Q,1=K,2=V
    const float* W = (m == 0) ? WQ : (m == 1) ? WK : WV;
    float acc[8];
#pragma unroll
    for (int i = 0; i < 8; i++) acc[i] = 0.f;
#pragma unroll 16
    for (int k = 0; k < 64; k++) {
        float wv = W[k * 64 + c];
#pragma unroll
        for (int i = 0; i < 8; i++) acc[i] = fmaf(hs[i * 64 + k], wv, acc[i]);
    }
    float* dstp = (m == 0) ? g_Q : (m == 1) ? g_K : g_V;
    float sv = 0.f;
#pragma unroll
    for (int i = 0; i < 8; i++) {
        dstp[(i0 + i) * 64 + c] = acc[i];
        sv += acc[i];
    }
    if (m == 2) g_SVp[b * 64 + c] = sv;   // plain store, no init required
}

// ---------------------------------------------------------------- fused edge
// Block = 64 edges. Phase 1: tiled GEMM Ehe = e_tile @ WE (f32x2 packed FMA).
// Phase 2: per-edge 3-way contraction + exp + scatter atomics.
__global__ void __launch_bounds__(256) edge_kernel(
    const float* __restrict__ e,
    const float* __restrict__ WE,
    const int* __restrict__ src,
    const int* __restrict__ dst) {
    __shared__ __align__(16) float WEs[64 * 64];     // [k][c]
    __shared__ __align__(16) float buf[64 * ESTR];   // es[k][edge], later ehe[edge][c]
    __shared__ int s_sh[64], d_sh[64];

    int tid = threadIdx.x;
    int base = blockIdx.x * 64;

    if (tid < 64) { s_sh[tid] = src[base + tid]; d_sh[tid] = dst[base + tid]; }

    // stage WE
    {
        float4* w4 = (float4*)WEs;
        const float4* g4 = (const float4*)WE;
        for (int idx = tid; idx < 1024; idx += 256) w4[idx] = g4[idx];
    }
    // stage e-tile transposed: es[k][edge]
    {
        int el = tid >> 2, seg = tid & 3;
        const float4* ge = (const float4*)(e + (size_t)(base + el) * 64 + seg * 16);
#pragma unroll
        for (int q = 0; q < 4; q++) {
            float4 v = ge[q];
            int k0 = seg * 16 + q * 4;
            buf[(k0 + 0) * ESTR + el] = v.x;
            buf[(k0 + 1) * ESTR + el] = v.y;
            buf[(k0 + 2) * ESTR + el] = v.z;
            buf[(k0 + 3) * ESTR + el] = v.w;
        }
    }
    __syncthreads();

    // claim prefetch (independent L2 load, hidden under the GEMM below)
    int w = tid >> 5, lane = tid & 31;
    int mk = w * 8 + (lane & 7);
    int cl = g_claim[s_sh[mk] * NN + d_sh[mk]];   // 0 if empty/self-loop

    // GEMM: thread (tx,ty) computes edges ty*4..+3  x  cols tx*4..+3
    int tx = tid & 15, ty = tid >> 4;
    unsigned long long acc[4][2];
#pragma unroll
    for (int i = 0; i < 4; i++) { acc[i][0] = 0ULL; acc[i][1] = 0ULL; }

#pragma unroll 16
    for (int k = 0; k < 64; k++) {
        float4 av = *reinterpret_cast<const float4*>(&buf[k * ESTR + ty * 4]);
        ulonglong2 bv = *reinterpret_cast<const ulonglong2*>(&WEs[k * 64 + tx * 4]);
        unsigned long long ad0, ad1, ad2, ad3;
        asm("mov.b64 %0, {%1,%1};" : "=l"(ad0) : "f"(av.x));
        asm("mov.b64 %0, {%1,%1};" : "=l"(ad1) : "f"(av.y));
        asm("mov.b64 %0, {%1,%1};" : "=l"(ad2) : "f"(av.z));
        asm("mov.b64 %0, {%1,%1};" : "=l"(ad3) : "f"(av.w));
        asm("fma.rn.f32x2 %0, %1, %2, %0;" : "+l"(acc[0][0]) : "l"(ad0), "l"(bv.x));
        asm("fma.rn.f32x2 %0, %1, %2, %0;" : "+l"(acc[0][1]) : "l"(ad0), "l"(bv.y));
        asm("fma.rn.f32x2 %0, %1, %2, %0;" : "+l"(acc[1][0]) : "l"(ad1), "l"(bv.x));
        asm("fma.rn.f32x2 %0, %1, %2, %0;" : "+l"(acc[1][1]) : "l"(ad1), "l"(bv.y));
        asm("fma.rn.f32x2 %0, %1, %2, %0;" : "+l"(acc[2][0]) : "l"(ad2), "l"(bv.x));
        asm("fma.rn.f32x2 %0, %1, %2, %0;" : "+l"(acc[2][1]) : "l"(ad2), "l"(bv.y));
        asm("fma.rn.f32x2 %0, %1, %2, %0;" : "+l"(acc[3][0]) : "l"(ad3), "l"(bv.x));
        asm("fma.rn.f32x2 %0, %1, %2, %0;" : "+l"(acc[3][1]) : "l"(ad3), "l"(bv.y));
    }
    __syncthreads();  // all reads of es done before overwrite

#pragma unroll
    for (int i = 0; i < 4; i++) {
        float2 lo = *reinterpret_cast<float2*>(&acc[i][0]);
        float2 hi = *reinterpret_cast<float2*>(&acc[i][1]);
        float4 o = make_float4(lo.x, lo.y, hi.x, hi.y);
        *reinterpret_cast<float4*>(&buf[(ty * 4 + i) * ESTR + tx * 4]) = o;
    }
    __syncthreads();

    const float INVS = 0.35355339059327373f;  // 1/sqrt(8)
    const float SC   = 0.9090909090909091f;   // 1/(1+gamma)
    const float C0   = 0.09090909090909091f;  // gamma/(1+gamma)

#pragma unroll
    for (int i = 0; i < 8; i++) {
        int kl = w * 8 + i;
        int cv = __shfl_sync(0xffffffffu, cl, i);
        if (cv != base + kl + 1) continue;  // self-loop / superseded duplicate
        int s = s_sh[kl], d = d_sh[kl];
        float eh0 = buf[kl * ESTR + lane];
        float eh1 = buf[kl * ESTR + lane + 32];
        float p0 = eh0 * g_K[s * 64 + lane] * g_Q[d * 64 + lane];
        float p1 = eh1 * g_K[s * 64 + lane + 32] * g_Q[d * 64 + lane + 32];
#pragma unroll
        for (int off = 4; off; off >>= 1) {
            p0 += __shfl_xor_sync(0xffffffffu, p0, off);
            p1 += __shfl_xor_sync(0xffffffffu, p1, off);
        }
        float d0 = expf(fminf(fmaxf(p0 * INVS, -5.f), 5.f)) * SC - C0;
        float d1 = expf(fminf(fmaxf(p1 * INVS, -5.f), 5.f)) * SC - C0;
        atomicAdd(&g_acc[d * 64 + lane],      d0 * g_V[s * 64 + lane]);
        atomicAdd(&g_acc[d * 64 + lane + 32], d1 * g_V[s * 64 + lane + 32]);
        if ((lane & 7) == 0) {
            atomicAdd(&g_z[d * 8 + (lane >> 3)],     d0);
            atomicAdd(&g_z[d * 8 + 4 + (lane >> 3)], d1);
        }
    }
}

// --------------------------------------------------- finalize + state reset
// blocks 0..63: normalize output (16 node-rows each) and reset g_acc/g_z.
// blocks 64..79: reset the touched claim-map entries (64 KB instead of 4 MB).
__global__ void __launch_bounds__(256) final_kernel(
    float* __restrict__ out,
    const int* __restrict__ src,
    const int* __restrict__ dst) {
    int b = blockIdx.x;
    int tid = threadIdx.x;
    if (b >= 64) {
        int base = (b - 64) * 1024;
        for (int k = base + tid; k < base + 1024; k += 256) {
            int s = src[k], d = dst[k];
            if (s != d) g_claim[s * NN + d] = 0;   // benign dup-write race (same value)
        }
        return;
    }
    const float C0 = 0.09090909090909091f;

    // cooperative SV reduction: SV[c] = sum over 128 proj-block partials
    __shared__ float red[4][64];
    __shared__ float svs[64];
    {
        int c = tid & 63, q = tid >> 6;
        float partial = 0.f;
#pragma unroll 8
        for (int p = q * 32; p < q * 32 + 32; p++) partial += g_SVp[p * 64 + c];
        red[q][c] = partial;
    }
    __syncthreads();
    if (tid < 64) svs[tid] = red[0][tid] + red[1][tid] + red[2][tid] + red[3][tid];
    __syncthreads();

    // block handles node rows 16b .. 16b+15 (1024 floats = 256 float4)
    int idx4 = b * 256 + tid;
    int idx = idx4 * 4;
    int j = idx >> 6;
    int c0 = idx & 63;          // multiple of 4 -> all 4 lanes share a head
    int hh = c0 >> 3;
    float z = C0 * 1023.0f + g_z[j * 8 + hh] + 1e-6f;
    float rz = 1.0f / z;
    float4 a = ((const float4*)g_acc)[idx4];
    float4 v = ((const float4*)g_V)[idx4];
    float4 o;
    o.x = (C0 * (svs[c0 + 0] - v.x) + a.x) * rz;
    o.y = (C0 * (svs[c0 + 1] - v.y) + a.y) * rz;
    o.z = (C0 * (svs[c0 + 2] - v.z) + a.z) * rz;
    o.w = (C0 * (svs[c0 + 3] - v.w) + a.w) * rz;
    ((float4*)out)[idx4] = o;
    ((float4*)g_acc)[idx4] = make_float4(0.f, 0.f, 0.f, 0.f);  // self-reset

    __syncthreads();  // all g_z reads in this block done
    if (tid < 128) g_z[b * 128 + tid] = 0.f;  // reset this block's 16 rows x 8 heads
}

extern "C" void kernel_launch(void* const* d_in, const int* in_sizes, int n_in,
                              void* d_out, int out_size) {
    const float* h  = (const float*)d_in[0];
    const float* e  = (const float*)d_in[1];
    const float* WQ = (const float*)d_in[2];
    const float* WK = (const float*)d_in[3];
    const float* WE = (const float*)d_in[4];
    // d_in[5..7] = WQ2, WK2, WE2: unobservable (fake weights survive only
    // off-edge, where they equal the constant gamma/(1+gamma)).
    const float* WV = (const float*)d_in[8];
    const int* rs   = (const int*)d_in[9];
    const int* rd   = (const int*)d_in[10];
    float* out = (float*)d_out;

    proj_claim_kernel<<<144, 192>>>(h, WQ, WK, WV, rs, rd);
    edge_kernel<<<256, 256>>>(e, WE, rs, rd);
    final_kernel<<<80, 256>>>(out, rs, rd);
}